// round 1
// baseline (speedup 1.0000x reference)
#include <cuda_runtime.h>
#include <math.h>

// SoftVectorQuantizer: z[8,64,64,64] f32, embedding[4096,64] f32
// out = concat(z_q [8,64,64,64], entropy_loss (=0), indices[32768] as f32)
//
// z_q = l2norm( softmax( l2norm(z_row) . l2norm(emb)^T / tau ) @ l2norm(emb) )
// Key: l2norm at the end kills the softmax denominator -> single online pass,
// track only running max m (stability) and unnormalized accumulator.
// argmax(probs) == argmax(logits) -> track with m.

#define N_E   4096
#define D     64
#define HW    4096            // 64*64
#define B     8
#define NROWS (B * HW)        // 32768
#define NZ    (B * D * HW)    // 2097152 z_q elements

#define TN    32              // embeddings per shared tile

__device__ float g_embn[N_E * D];   // normalized embedding scratch

// --- normalize embedding rows: one warp per row ---
__global__ void norm_emb_kernel(const float* __restrict__ emb) {
    int e = blockIdx.x;
    int lane = threadIdx.x;  // 32
    float2 v = reinterpret_cast<const float2*>(emb + (size_t)e * D)[lane];
    float s = v.x * v.x + v.y * v.y;
    #pragma unroll
    for (int o = 16; o; o >>= 1) s += __shfl_xor_sync(0xffffffffu, s, o);
    float inv = 1.0f / fmaxf(sqrtf(s), 1e-12f);
    float2 r; r.x = v.x * inv; r.y = v.y * inv;
    reinterpret_cast<float2*>(g_embn + (size_t)e * D)[lane] = r;
}

// --- main fused kernel: one thread per row, online softmax over 4096 embs ---
__global__ __launch_bounds__(64)
void svq_kernel(const float* __restrict__ z, float* __restrict__ out) {
    __shared__ float4 semb[TN * (D / 4)];   // 8 KB tile of normalized emb

    const int t = threadIdx.x;              // 64 threads = 64 rows
    const int n = blockIdx.x * 64 + t;      // row id (block never crosses b)
    const int b = n >> 12;
    const int hw = n & (HW - 1);

    // load + normalize this row's z (channel stride HW -> coalesced across threads)
    const float* zb = z + (size_t)b * (D * HW) + hw;
    float zr[D];
    float ss = 0.0f;
    #pragma unroll
    for (int c = 0; c < D; c++) {
        zr[c] = zb[(size_t)c * HW];
        ss += zr[c] * zr[c];
    }
    {
        float inv = 1.0f / fmaxf(sqrtf(ss), 1e-12f);
        #pragma unroll
        for (int c = 0; c < D; c++) zr[c] *= inv;
    }

    float acc[D];
    #pragma unroll
    for (int c = 0; c < D; c++) acc[c] = 0.0f;

    float m = -INFINITY;
    int best = 0;
    const float Cexp = 1.44269504f / 0.07f;   // log2(e)/tau

    for (int tb = 0; tb < N_E; tb += TN) {
        __syncthreads();
        // cooperative tile load: TN*16 float4 over 64 threads -> 8 each
        #pragma unroll
        for (int i = 0; i < (TN * (D / 4)) / 64; i++) {
            int j = i * 64 + t;
            semb[j] = reinterpret_cast<const float4*>(g_embn)[(size_t)tb * (D / 4) + j];
        }
        __syncthreads();

        #pragma unroll 1
        for (int e = 0; e < TN; e++) {
            const float4* er = semb + e * (D / 4);
            float d0 = 0.f, d1 = 0.f, d2 = 0.f, d3 = 0.f;
            #pragma unroll
            for (int k = 0; k < D / 4; k++) {
                float4 v = er[k];
                d0 += zr[4 * k + 0] * v.x;
                d1 += zr[4 * k + 1] * v.y;
                d2 += zr[4 * k + 2] * v.z;
                d3 += zr[4 * k + 3] * v.w;
            }
            float dot = (d0 + d1) + (d2 + d3);

            if (dot > m) {
                // new max: rescale accumulator, p == 1
                float s = exp2f((m - dot) * Cexp);
                m = dot;
                best = tb + e;
                #pragma unroll
                for (int k = 0; k < D / 4; k++) {
                    float4 v = er[k];
                    acc[4 * k + 0] = acc[4 * k + 0] * s + v.x;
                    acc[4 * k + 1] = acc[4 * k + 1] * s + v.y;
                    acc[4 * k + 2] = acc[4 * k + 2] * s + v.z;
                    acc[4 * k + 3] = acc[4 * k + 3] * s + v.w;
                }
            } else {
                float p = exp2f((dot - m) * Cexp);
                #pragma unroll
                for (int k = 0; k < D / 4; k++) {
                    float4 v = er[k];
                    acc[4 * k + 0] += p * v.x;
                    acc[4 * k + 1] += p * v.y;
                    acc[4 * k + 2] += p * v.z;
                    acc[4 * k + 3] += p * v.w;
                }
            }
        }
    }

    // final l2 normalize (this absorbs the softmax denominator)
    float sq = 0.0f;
    #pragma unroll
    for (int c = 0; c < D; c++) sq += acc[c] * acc[c];
    float invq = 1.0f / fmaxf(sqrtf(sq), 1e-12f);

    float* ob = out + (size_t)b * (D * HW) + hw;
    #pragma unroll
    for (int c = 0; c < D; c++) ob[(size_t)c * HW] = acc[c] * invq;

    // indices (as f32) and entropy loss
    out[NZ + 1 + n] = (float)best;
    if (n == 0) out[NZ] = 0.0f;
}

extern "C" void kernel_launch(void* const* d_in, const int* in_sizes, int n_in,
                              void* d_out, int out_size) {
    const float* z   = (const float*)d_in[0];
    const float* emb = (const float*)d_in[1];
    float* out = (float*)d_out;
    (void)in_sizes; (void)n_in; (void)out_size;

    norm_emb_kernel<<<N_E, 32>>>(emb);
    svq_kernel<<<NROWS / 64, 64>>>(z, out);
}

// round 3
// speedup vs baseline: 2.4203x; 2.4203x over previous
#include <cuda_runtime.h>
#include <math.h>
#include <stdint.h>

// ============================================================================
// SoftVectorQuantizer via mma.sync tf32 (sm_103 base target — no tcgen05,
// the harness emits compute_103 PTX which rejects sm_103a-only instructions).
//
// z[8,64,64,64] f32, embedding[4096,64] f32.
// out = concat(z_q[2097152], entropy(=0), indices[32768] as f32)
//
// Algebra: all rows unit-norm -> logits <= 1 -> fixed softmax shift (exp((s-1)/tau)),
// final l2norm absorbs softmax denominator. argmax via tf32 top-2 + exact refine.
// ============================================================================

#define N_E     4096
#define D       64
#define HW      4096
#define NZ      2097152
#define NROWS   32768
#define CTAS    256          // 128 rows per CTA
#define THREADS 128          // 4 warps x 32 rows
#define NT      64           // embedding tiles of 64
#define CE      20.60992529f // log2(e)/0.07

// SMEM (uint32 elements): K-frags 2 bufs @ 4096, V-frags 2 bufs @ 4096
#define KF(buf) ((buf) * 4096)
#define VF(buf) (8192 + (buf) * 4096)
#define SMEM_BYTES 65536

__device__ float g_embn[N_E * D];
__device__ int   g_cand[2][NROWS];

__device__ __forceinline__ uint32_t cvt_tf32(float x) {
    uint32_t r; asm("cvt.rna.tf32.f32 %0, %1;" : "=r"(r) : "f"(x)); return r;
}
__device__ __forceinline__ float ex2f(float x) {
    float r; asm("ex2.approx.f32 %0, %1;" : "=f"(r) : "f"(x)); return r;
}
__device__ __forceinline__ void mma_tf32(float c[4], const uint32_t a[4],
                                         uint32_t b0, uint32_t b1) {
    asm volatile(
        "mma.sync.aligned.m16n8k8.row.col.f32.tf32.tf32.f32 "
        "{%0,%1,%2,%3},{%4,%5,%6,%7},{%8,%9},{%0,%1,%2,%3};"
        : "+f"(c[0]), "+f"(c[1]), "+f"(c[2]), "+f"(c[3])
        : "r"(a[0]), "r"(a[1]), "r"(a[2]), "r"(a[3]), "r"(b0), "r"(b1));
}

// scatter one 64x64 emb tile (held in regs) into K-frag + V-frag SMEM layouts
__device__ __forceinline__ void fill_frags(uint32_t* kf, uint32_t* vf,
                                           const float4* pre, int e, int h) {
    #pragma unroll
    for (int i = 0; i < 8; i++) {
        float v4[4] = {pre[i].x, pre[i].y, pre[i].z, pre[i].w};
        #pragma unroll
        for (int c = 0; c < 4; c++) {
            int k = h * 32 + i * 4 + c;
            uint32_t tv = cvt_tf32(v4[c]);
            // GEMM1 B-frag: n = e (lane>>2 = e&7), kdim = k
            kf[(e >> 3) * 512 + (k >> 3) * 64 +
               ((e & 7) << 3) + ((k & 3) << 1) + ((k >> 2) & 1)] = tv;
            // GEMM2 B-frag: n = d(=k), kdim = e
            vf[(k >> 3) * 512 + (e >> 3) * 64 +
               ((k & 7) << 3) + ((e & 3) << 1) + ((e >> 2) & 1)] = tv;
        }
    }
}

// ---------------------------------------------------------------------------
__global__ void norm_emb_kernel(const float* __restrict__ emb) {
    int e = blockIdx.x, lane = threadIdx.x;
    float2 v = reinterpret_cast<const float2*>(emb + (size_t)e * D)[lane];
    float s = v.x * v.x + v.y * v.y;
    #pragma unroll
    for (int o = 16; o; o >>= 1) s += __shfl_xor_sync(0xffffffffu, s, o);
    float inv = 1.0f / fmaxf(sqrtf(s), 1e-12f);
    float2 r; r.x = v.x * inv; r.y = v.y * inv;
    reinterpret_cast<float2*>(g_embn + (size_t)e * D)[lane] = r;
}

// ---------------------------------------------------------------------------
__global__ void __launch_bounds__(THREADS, 2)
svq_main_kernel(const float* __restrict__ z, float* __restrict__ out) {
    extern __shared__ uint32_t smem[];
    const int tid  = threadIdx.x;
    const int w    = tid >> 5;
    const int lane = tid & 31;
    const int q    = lane & 3;       // thread-in-group
    const int r    = lane >> 2;      // group id (row)
    const unsigned FULL = 0xffffffffu;

    const int n0  = blockIdx.x * 128 + w * 32;   // first row of this warp
    const int bb  = n0 >> 12;
    const int hw0 = n0 & (HW - 1);
    const float* zbase = z + (size_t)bb * D * HW + hw0;

    // ---- load Q rows, l2-normalize, convert to tf32 A-fragments ----
    // qa[mi][j][areg]: A frag for m16 tile mi, k-step j
    uint32_t qa[2][8][4];
    float ssq[4] = {0.f, 0.f, 0.f, 0.f};
    #pragma unroll
    for (int mi = 0; mi < 2; mi++)
        #pragma unroll
        for (int j = 0; j < 8; j++)
            #pragma unroll
            for (int a = 0; a < 4; a++) {
                int row = mi * 16 + r + (a & 1) * 8;
                int k   = j * 8 + q + ((a & 2) ? 4 : 0);
                float v = zbase[(size_t)k * HW + row];
                qa[mi][j][a] = __float_as_uint(v);
                ssq[mi * 2 + (a & 1)] += v * v;
            }
    #pragma unroll
    for (int s = 0; s < 4; s++) {
        ssq[s] += __shfl_xor_sync(FULL, ssq[s], 1);
        ssq[s] += __shfl_xor_sync(FULL, ssq[s], 2);
        ssq[s] = 1.0f / fmaxf(sqrtf(ssq[s]), 1e-12f);
    }
    #pragma unroll
    for (int mi = 0; mi < 2; mi++)
        #pragma unroll
        for (int j = 0; j < 8; j++)
            #pragma unroll
            for (int a = 0; a < 4; a++)
                qa[mi][j][a] =
                    cvt_tf32(__uint_as_float(qa[mi][j][a]) * ssq[mi * 2 + (a & 1)]);

    // ---- O accumulators + top-2 state ----
    float o[2][8][4];
    #pragma unroll
    for (int mi = 0; mi < 2; mi++)
        #pragma unroll
        for (int di = 0; di < 8; di++)
            #pragma unroll
            for (int c = 0; c < 4; c++) o[mi][di][c] = 0.f;
    float m1[4] = {-1e30f, -1e30f, -1e30f, -1e30f};
    float m2[4] = {-1e30f, -1e30f, -1e30f, -1e30f};
    int   i1[4] = {0, 0, 0, 0}, i2[4] = {0, 0, 0, 0};

    // ---- fill tile 0 ----
    const int ef = tid >> 1, hf = tid & 1;
    {
        float4 pre[8];
        const float4* src = reinterpret_cast<const float4*>(
            g_embn + (size_t)ef * D + hf * 32);
        #pragma unroll
        for (int i = 0; i < 8; i++) pre[i] = src[i];
        fill_frags(smem + KF(0), smem + VF(0), pre, ef, hf);
    }
    __syncthreads();

    const int srcA = (lane & ~3) | ((lane >> 1) & 1);
    const int srcB = srcA | 2;

    for (int t = 0; t < NT; t++) {
        const int cur = t & 1;
        const uint32_t* kf = smem + KF(cur);
        const uint32_t* vf = smem + VF(cur);

        // prefetch next tile (LDGs overlap the compute below)
        float4 pre[8];
        if (t < NT - 1) {
            const float4* src = reinterpret_cast<const float4*>(
                g_embn + (size_t)(t + 1) * 64 * D + (size_t)ef * D + hf * 32);
            #pragma unroll
            for (int i = 0; i < 8; i++) pre[i] = src[i];
        }

        #pragma unroll
        for (int ni = 0; ni < 8; ni++) {
            // GEMM1: S chunk [32 x 8]
            float s[2][4] = {{0.f,0.f,0.f,0.f},{0.f,0.f,0.f,0.f}};
            #pragma unroll
            for (int j = 0; j < 8; j++) {
                uint2 bk = *reinterpret_cast<const uint2*>(
                    kf + ni * 512 + j * 64 + lane * 2);
                mma_tf32(s[0], qa[0][j], bk.x, bk.y);
                mma_tf32(s[1], qa[1][j], bk.x, bk.y);
            }
            // top-2 + exp + tf32
            const int colbase = t * 64 + ni * 8 + 2 * q;
            uint32_t p[2][4];
            #pragma unroll
            for (int mi = 0; mi < 2; mi++)
                #pragma unroll
                for (int c = 0; c < 4; c++) {
                    float sv = s[mi][c];
                    int slot = mi * 2 + (c >> 1);
                    int col  = colbase + (c & 1);
                    if (sv > m2[slot]) {
                        if (sv > m1[slot]) {
                            m2[slot] = m1[slot]; i2[slot] = i1[slot];
                            m1[slot] = sv;       i1[slot] = col;
                        } else { m2[slot] = sv; i2[slot] = col; }
                    }
                    p[mi][c] = cvt_tf32(ex2f(fmaf(sv, CE, -CE)));
                }
            // remap P: C-fragment -> A-fragment (intra-quad shuffles)
            uint32_t a[2][4];
            #pragma unroll
            for (int mi = 0; mi < 2; mi++) {
                uint32_t t0, t1;
                t0 = __shfl_sync(FULL, p[mi][0], srcA);
                t1 = __shfl_sync(FULL, p[mi][1], srcA);
                a[mi][0] = (lane & 1) ? t1 : t0;
                t0 = __shfl_sync(FULL, p[mi][2], srcA);
                t1 = __shfl_sync(FULL, p[mi][3], srcA);
                a[mi][1] = (lane & 1) ? t1 : t0;
                t0 = __shfl_sync(FULL, p[mi][0], srcB);
                t1 = __shfl_sync(FULL, p[mi][1], srcB);
                a[mi][2] = (lane & 1) ? t1 : t0;
                t0 = __shfl_sync(FULL, p[mi][2], srcB);
                t1 = __shfl_sync(FULL, p[mi][3], srcB);
                a[mi][3] = (lane & 1) ? t1 : t0;
            }
            // GEMM2: O += P * V
            #pragma unroll
            for (int di = 0; di < 8; di++) {
                uint2 bv = *reinterpret_cast<const uint2*>(
                    vf + di * 512 + ni * 64 + lane * 2);
                mma_tf32(o[0][di], a[0], bv.x, bv.y);
                mma_tf32(o[1][di], a[1], bv.x, bv.y);
            }
        }
        __syncthreads();
        if (t < NT - 1) {
            fill_frags(smem + KF(cur ^ 1), smem + VF(cur ^ 1), pre, ef, hf);
        }
        __syncthreads();
    }

    // ---- O: per-row l2norm + store ----
    float oss[4] = {0.f, 0.f, 0.f, 0.f};
    #pragma unroll
    for (int mi = 0; mi < 2; mi++)
        #pragma unroll
        for (int di = 0; di < 8; di++) {
            oss[mi * 2 + 0] += o[mi][di][0] * o[mi][di][0] + o[mi][di][1] * o[mi][di][1];
            oss[mi * 2 + 1] += o[mi][di][2] * o[mi][di][2] + o[mi][di][3] * o[mi][di][3];
        }
    #pragma unroll
    for (int s = 0; s < 4; s++) {
        oss[s] += __shfl_xor_sync(FULL, oss[s], 1);
        oss[s] += __shfl_xor_sync(FULL, oss[s], 2);
        oss[s] = 1.0f / fmaxf(sqrtf(oss[s]), 1e-12f);
    }
    float* ob = out + (size_t)bb * D * HW + hw0;
    #pragma unroll
    for (int mi = 0; mi < 2; mi++)
        #pragma unroll
        for (int di = 0; di < 8; di++) {
            int d0 = di * 8 + 2 * q;
            int rl = mi * 16 + r, rh = rl + 8;
            ob[(size_t)d0 * HW + rl]       = o[mi][di][0] * oss[mi * 2];
            ob[(size_t)(d0 + 1) * HW + rl] = o[mi][di][1] * oss[mi * 2];
            ob[(size_t)d0 * HW + rh]       = o[mi][di][2] * oss[mi * 2 + 1];
            ob[(size_t)(d0 + 1) * HW + rh] = o[mi][di][3] * oss[mi * 2 + 1];
        }

    // ---- merge top-2 across the 4 lanes of each row group ----
    #pragma unroll
    for (int s = 0; s < 4; s++) {
        #pragma unroll
        for (int off = 1; off <= 2; off++) {
            float om1 = __shfl_xor_sync(FULL, m1[s], off);
            int   oi1 = __shfl_xor_sync(FULL, i1[s], off);
            float om2 = __shfl_xor_sync(FULL, m2[s], off);
            int   oi2 = __shfl_xor_sync(FULL, i2[s], off);
            if (om1 > m1[s] || (om1 == m1[s] && oi1 < i1[s])) {
                float tm = m1[s]; int ti = i1[s];
                m1[s] = om1; i1[s] = oi1;
                om1 = tm; oi1 = ti;
            }
            // second = best of {m2, om1, om2-if-om1-was-promoted...}: om2 <= om1
            if (om1 > m2[s] || (om1 == m2[s] && oi1 < i2[s])) { m2[s] = om1; i2[s] = oi1; }
            if (om2 > m2[s] || (om2 == m2[s] && oi2 < i2[s])) { m2[s] = om2; i2[s] = oi2; }
        }
    }
    if (q == 0) {
        #pragma unroll
        for (int s = 0; s < 4; s++) {
            int n = n0 + (s >> 1) * 16 + (s & 1) * 8 + r;
            g_cand[0][n] = i1[s];
            g_cand[1][n] = i2[s];
        }
    }
}

// ---------------------------------------------------------------------------
// exact fp32 argmax refinement over tf32 top-2 candidates
// ---------------------------------------------------------------------------
__global__ void refine_kernel(const float* __restrict__ z, float* __restrict__ out) {
    int n = blockIdx.x * 256 + threadIdx.x;
    int b = n >> 12, hw = n & (HW - 1);
    const float* zb = z + (size_t)b * (D * HW) + hw;
    float zr[D];
    #pragma unroll
    for (int c = 0; c < D; c++) zr[c] = zb[(size_t)c * HW];

    float bd = -1e30f; int bi = 0x7fffffff;
    #pragma unroll
    for (int k = 0; k < 2; k++) {
        int e = g_cand[k][n];
        const float4* er = reinterpret_cast<const float4*>(g_embn + (size_t)e * D);
        float d0 = 0.f, d1 = 0.f, d2 = 0.f, d3 = 0.f;
        #pragma unroll
        for (int t = 0; t < D / 4; t++) {
            float4 v = er[t];
            d0 += zr[4 * t + 0] * v.x;
            d1 += zr[4 * t + 1] * v.y;
            d2 += zr[4 * t + 2] * v.z;
            d3 += zr[4 * t + 3] * v.w;
        }
        float dot = (d0 + d1) + (d2 + d3);
        if (dot > bd || (dot == bd && e < bi)) { bd = dot; bi = e; }
    }
    out[NZ + 1 + n] = (float)bi;
    if (n == 0) out[NZ] = 0.0f;
}

// ---------------------------------------------------------------------------
extern "C" void kernel_launch(void* const* d_in, const int* in_sizes, int n_in,
                              void* d_out, int out_size) {
    const float* z   = (const float*)d_in[0];
    const float* emb = (const float*)d_in[1];
    float* out = (float*)d_out;
    (void)in_sizes; (void)n_in; (void)out_size;

    cudaFuncSetAttribute(svq_main_kernel,
                         cudaFuncAttributeMaxDynamicSharedMemorySize, SMEM_BYTES);

    norm_emb_kernel<<<N_E, 32>>>(emb);
    svq_main_kernel<<<CTAS, THREADS, SMEM_BYTES>>>(z, out);
    refine_kernel<<<NROWS / 256, 256>>>(z, out);
}

// round 4
// speedup vs baseline: 4.2205x; 1.7438x over previous
#include <cuda_runtime.h>
#include <cuda_bf16.h>
#include <math.h>
#include <stdint.h>

// ============================================================================
// SoftVectorQuantizer via mma.sync (tf32 GEMM1 + bf16 GEMM2), flash-style.
// z[8,64,64,64] f32, embedding[4096,64] f32.
// out = concat(z_q[2097152], entropy(=0), indices[32768] as f32)
//
// Algebra: all rows unit-norm -> logits <= 1 -> fixed softmax shift exp((s-1)/tau);
// final l2norm absorbs the softmax denominator. argmax via tf32 top-2 + exact refine.
// f16-family k16 A-fragment == two stacked n8 C-fragments -> P needs NO shuffles.
// ============================================================================

#define N_E     4096
#define D       64
#define HW      4096
#define NZ      2097152
#define NROWS   32768
#define CTAS    128          // 256 rows per CTA
#define THREADS 256          // 8 warps x 32 rows
#define NT      64           // embedding tiles of 64
#define CE      20.60992529f // log2(e)/0.07

__device__ float    g_embn[N_E * D];          // normalized embedding (refine)
__device__ uint32_t g_kf[NT * 4096];          // tf32 K-fragments, tile-blocked
__device__ uint16_t g_vf[NT * 4096];          // bf16 V-fragments, tile-blocked
__device__ int      g_cand[2][NROWS];

// fragment-layout index helpers (uint32 units within a 64x64 tile)
__host__ __device__ __forceinline__ int kf_idx(int e, int k) {
    // load: uint4 at ni*512 + jp*128 + lane*4 ; lane = (e&7)*4 + (k&3)
    return (e >> 3) * 512 + (k >> 4) * 128 +
           (((e & 7) * 4 + (k & 3)) * 4) + ((k >> 3) & 1) * 2 + ((k >> 2) & 1);
}
__host__ __device__ __forceinline__ int vf_half_idx(int e, int d) {
    // load: uint2 at di*256 + p*64 + lane*2 ; k-dim = e, n-dim = d
    int ep = e & 15;
    int u32 = (d >> 3) * 256 + (e >> 4) * 64 +
              (((d & 7) * 4 + ((ep & 7) >> 1)) * 2) + (ep >> 3);
    return u32 * 2 + (ep & 1);
}

__device__ __forceinline__ uint32_t cvt_tf32(float x) {
    uint32_t r; asm("cvt.rna.tf32.f32 %0, %1;" : "=r"(r) : "f"(x)); return r;
}
__device__ __forceinline__ float ex2f(float x) {
    float r; asm("ex2.approx.f32 %0, %1;" : "=f"(r) : "f"(x)); return r;
}
__device__ __forceinline__ uint32_t pack_bf16(float lo, float hi) {
    uint32_t r; asm("cvt.rn.bf16x2.f32 %0, %1, %2;" : "=r"(r) : "f"(hi), "f"(lo));
    return r;
}
__device__ __forceinline__ uint32_t smem_u32(const void* p) {
    uint32_t a;
    asm("{ .reg .u64 t; cvta.to.shared.u64 t, %1; cvt.u32.u64 %0, t; }"
        : "=r"(a) : "l"(p));
    return a;
}
__device__ __forceinline__ void cpa16(uint32_t dst, const void* src) {
    asm volatile("cp.async.cg.shared.global [%0], [%1], 16;" :: "r"(dst), "l"(src));
}
__device__ __forceinline__ void mma_tf32(float c[4], const uint32_t a[4],
                                         uint32_t b0, uint32_t b1) {
    asm volatile(
        "mma.sync.aligned.m16n8k8.row.col.f32.tf32.tf32.f32 "
        "{%0,%1,%2,%3},{%4,%5,%6,%7},{%8,%9},{%0,%1,%2,%3};"
        : "+f"(c[0]), "+f"(c[1]), "+f"(c[2]), "+f"(c[3])
        : "r"(a[0]), "r"(a[1]), "r"(a[2]), "r"(a[3]), "r"(b0), "r"(b1));
}
__device__ __forceinline__ void mma_bf16(float c[4], const uint32_t a[4],
                                         uint32_t b0, uint32_t b1) {
    asm volatile(
        "mma.sync.aligned.m16n8k16.row.col.f32.bf16.bf16.f32 "
        "{%0,%1,%2,%3},{%4,%5,%6,%7},{%8,%9},{%0,%1,%2,%3};"
        : "+f"(c[0]), "+f"(c[1]), "+f"(c[2]), "+f"(c[3])
        : "r"(a[0]), "r"(a[1]), "r"(a[2]), "r"(a[3]), "r"(b0), "r"(b1));
}

// ---------------------------------------------------------------------------
// prep: normalize embedding rows + scatter into frag layouts (once)
// ---------------------------------------------------------------------------
__global__ void prep_kernel(const float* __restrict__ emb) {
    int e = blockIdx.x * 4 + (threadIdx.x >> 5);
    int lane = threadIdx.x & 31;
    float2 v = reinterpret_cast<const float2*>(emb + (size_t)e * D)[lane];
    float s = v.x * v.x + v.y * v.y;
    #pragma unroll
    for (int o = 16; o; o >>= 1) s += __shfl_xor_sync(0xffffffffu, s, o);
    float inv = 1.0f / fmaxf(sqrtf(s), 1e-12f);
    float2 r; r.x = v.x * inv; r.y = v.y * inv;
    reinterpret_cast<float2*>(g_embn + (size_t)e * D)[lane] = r;

    int tile = e >> 6, el = e & 63;
    int k0 = 2 * lane, k1 = 2 * lane + 1;
    g_kf[tile * 4096 + kf_idx(el, k0)] = cvt_tf32(r.x);
    g_kf[tile * 4096 + kf_idx(el, k1)] = cvt_tf32(r.y);
    __nv_bfloat16 b0 = __float2bfloat16(r.x), b1 = __float2bfloat16(r.y);
    g_vf[tile * 4096 + vf_half_idx(el, k0)] = *reinterpret_cast<uint16_t*>(&b0);
    g_vf[tile * 4096 + vf_half_idx(el, k1)] = *reinterpret_cast<uint16_t*>(&b1);
}

// ---------------------------------------------------------------------------
// main fused kernel
// ---------------------------------------------------------------------------
__global__ void __launch_bounds__(THREADS)
svq_main_kernel(const float* __restrict__ z, float* __restrict__ out) {
    __shared__ uint32_t s_kf[2][4096];   // 32 KB
    __shared__ uint32_t s_vf[2][2048];   // 16 KB

    const int tid  = threadIdx.x;
    const int w    = tid >> 5;
    const int lane = tid & 31;
    const int q    = lane & 3;
    const int r    = lane >> 2;
    const unsigned FULL = 0xffffffffu;

    const uint32_t kf_s[2] = {smem_u32(&s_kf[0][0]), smem_u32(&s_kf[1][0])};
    const uint32_t vf_s[2] = {smem_u32(&s_vf[0][0]), smem_u32(&s_vf[1][0])};

    // ---- kick off async copies of tiles 0 and 1 ----
    {
        #pragma unroll
        for (int i = 0; i < 4; i++)
            cpa16(kf_s[0] + (i * 256 + tid) * 16,
                  (const char*)g_kf + (i * 256 + tid) * 16);
        #pragma unroll
        for (int i = 0; i < 2; i++)
            cpa16(vf_s[0] + (i * 256 + tid) * 16,
                  (const char*)g_vf + (i * 256 + tid) * 16);
        asm volatile("cp.async.commit_group;");
        #pragma unroll
        for (int i = 0; i < 4; i++)
            cpa16(kf_s[1] + (i * 256 + tid) * 16,
                  (const char*)g_kf + 16384 + (i * 256 + tid) * 16);
        #pragma unroll
        for (int i = 0; i < 2; i++)
            cpa16(vf_s[1] + (i * 256 + tid) * 16,
                  (const char*)g_vf + 8192 + (i * 256 + tid) * 16);
        asm volatile("cp.async.commit_group;");
    }

    // ---- Q: load 32 rows/warp, l2-normalize, tf32 A-frags (overlaps copies) ----
    const int n0  = blockIdx.x * 256 + w * 32;
    const int bb  = n0 >> 12;
    const int hw0 = n0 & (HW - 1);
    const float* zbase = z + (size_t)bb * D * HW + hw0;

    uint32_t qa[2][8][4];
    float ssq[4] = {0.f, 0.f, 0.f, 0.f};
    #pragma unroll
    for (int mi = 0; mi < 2; mi++)
        #pragma unroll
        for (int j = 0; j < 8; j++)
            #pragma unroll
            for (int a = 0; a < 4; a++) {
                int row = mi * 16 + r + (a & 1) * 8;
                int k   = j * 8 + q + ((a & 2) ? 4 : 0);
                float v = zbase[(size_t)k * HW + row];
                qa[mi][j][a] = __float_as_uint(v);
                ssq[mi * 2 + (a & 1)] += v * v;
            }
    #pragma unroll
    for (int s = 0; s < 4; s++) {
        ssq[s] += __shfl_xor_sync(FULL, ssq[s], 1);
        ssq[s] += __shfl_xor_sync(FULL, ssq[s], 2);
        ssq[s] = 1.0f / fmaxf(sqrtf(ssq[s]), 1e-12f);
    }
    #pragma unroll
    for (int mi = 0; mi < 2; mi++)
        #pragma unroll
        for (int j = 0; j < 8; j++)
            #pragma unroll
            for (int a = 0; a < 4; a++)
                qa[mi][j][a] =
                    cvt_tf32(__uint_as_float(qa[mi][j][a]) * ssq[mi * 2 + (a & 1)]);

    float o[2][8][4];
    #pragma unroll
    for (int mi = 0; mi < 2; mi++)
        #pragma unroll
        for (int di = 0; di < 8; di++)
            #pragma unroll
            for (int c = 0; c < 4; c++) o[mi][di][c] = 0.f;
    float m1[4] = {-1e30f, -1e30f, -1e30f, -1e30f};
    float m2[4] = {-1e30f, -1e30f, -1e30f, -1e30f};
    int   i1[4] = {0, 0, 0, 0}, i2[4] = {0, 0, 0, 0};

    for (int t = 0; t < NT; t++) {
        const int cur = t & 1;
        if (t + 1 < NT) asm volatile("cp.async.wait_group 1;");
        else            asm volatile("cp.async.wait_group 0;");
        __syncthreads();

        const uint32_t* ks = s_kf[cur];
        const uint32_t* vs = s_vf[cur];

        #pragma unroll
        for (int pi = 0; pi < 4; pi++) {
            // GEMM1: two n8 chunks (16 embeddings)
            float s[2][2][4];
            #pragma unroll
            for (int nih = 0; nih < 2; nih++)
                #pragma unroll
                for (int mi = 0; mi < 2; mi++)
                    #pragma unroll
                    for (int c = 0; c < 4; c++) s[nih][mi][c] = 0.f;
            #pragma unroll
            for (int nih = 0; nih < 2; nih++) {
                const int ni = pi * 2 + nih;
                #pragma unroll
                for (int jp = 0; jp < 4; jp++) {
                    uint4 bk = *reinterpret_cast<const uint4*>(
                        ks + ni * 512 + jp * 128 + lane * 4);
                    mma_tf32(s[nih][0], qa[0][2 * jp],     bk.x, bk.y);
                    mma_tf32(s[nih][1], qa[1][2 * jp],     bk.x, bk.y);
                    mma_tf32(s[nih][0], qa[0][2 * jp + 1], bk.z, bk.w);
                    mma_tf32(s[nih][1], qa[1][2 * jp + 1], bk.z, bk.w);
                }
            }
            // epilogue: top-2 + exp -> bf16 A-frags (no shuffles needed!)
            uint32_t a[2][4];
            #pragma unroll
            for (int mi = 0; mi < 2; mi++)
                #pragma unroll
                for (int nih = 0; nih < 2; nih++) {
                    float p[4];
                    #pragma unroll
                    for (int c = 0; c < 4; c++) {
                        float sv = s[nih][mi][c];
                        int slot = mi * 2 + (c >> 1);
                        int col  = t * 64 + (pi * 2 + nih) * 8 + 2 * q + (c & 1);
                        if (sv > m2[slot]) {
                            if (sv > m1[slot]) {
                                m2[slot] = m1[slot]; i2[slot] = i1[slot];
                                m1[slot] = sv;       i1[slot] = col;
                            } else { m2[slot] = sv; i2[slot] = col; }
                        }
                        p[c] = ex2f(fmaf(sv, CE, -CE));
                    }
                    a[mi][nih * 2 + 0] = pack_bf16(p[0], p[1]);
                    a[mi][nih * 2 + 1] = pack_bf16(p[2], p[3]);
                }
            // GEMM2: O += P(16) * V(16 x 64), bf16 k16
            #pragma unroll
            for (int di = 0; di < 8; di++) {
                uint2 bv = *reinterpret_cast<const uint2*>(
                    vs + di * 256 + pi * 64 + lane * 2);
                mma_bf16(o[0][di], a[0], bv.x, bv.y);
                mma_bf16(o[1][di], a[1], bv.x, bv.y);
            }
        }
        __syncthreads();

        // issue copy of tile t+2 into the buffer just freed
        if (t + 2 < NT) {
            const char* gk = (const char*)g_kf + (size_t)(t + 2) * 16384;
            const char* gv = (const char*)g_vf + (size_t)(t + 2) * 8192;
            #pragma unroll
            for (int i = 0; i < 4; i++)
                cpa16(kf_s[cur] + (i * 256 + tid) * 16, gk + (i * 256 + tid) * 16);
            #pragma unroll
            for (int i = 0; i < 2; i++)
                cpa16(vf_s[cur] + (i * 256 + tid) * 16, gv + (i * 256 + tid) * 16);
            asm volatile("cp.async.commit_group;");
        }
    }

    // ---- O: per-row l2norm + store ----
    float oss[4] = {0.f, 0.f, 0.f, 0.f};
    #pragma unroll
    for (int mi = 0; mi < 2; mi++)
        #pragma unroll
        for (int di = 0; di < 8; di++) {
            oss[mi * 2 + 0] += o[mi][di][0] * o[mi][di][0] + o[mi][di][1] * o[mi][di][1];
            oss[mi * 2 + 1] += o[mi][di][2] * o[mi][di][2] + o[mi][di][3] * o[mi][di][3];
        }
    #pragma unroll
    for (int s = 0; s < 4; s++) {
        oss[s] += __shfl_xor_sync(FULL, oss[s], 1);
        oss[s] += __shfl_xor_sync(FULL, oss[s], 2);
        oss[s] = 1.0f / fmaxf(sqrtf(oss[s]), 1e-12f);
    }
    float* ob = out + (size_t)bb * D * HW + hw0;
    #pragma unroll
    for (int mi = 0; mi < 2; mi++)
        #pragma unroll
        for (int di = 0; di < 8; di++) {
            int d0 = di * 8 + 2 * q;
            int rl = mi * 16 + r, rh = rl + 8;
            ob[(size_t)d0 * HW + rl]       = o[mi][di][0] * oss[mi * 2];
            ob[(size_t)(d0 + 1) * HW + rl] = o[mi][di][1] * oss[mi * 2];
            ob[(size_t)d0 * HW + rh]       = o[mi][di][2] * oss[mi * 2 + 1];
            ob[(size_t)(d0 + 1) * HW + rh] = o[mi][di][3] * oss[mi * 2 + 1];
        }

    // ---- merge top-2 across the 4 quad lanes of each row ----
    #pragma unroll
    for (int s = 0; s < 4; s++) {
        #pragma unroll
        for (int off = 1; off <= 2; off++) {
            float om1 = __shfl_xor_sync(FULL, m1[s], off);
            int   oi1 = __shfl_xor_sync(FULL, i1[s], off);
            float om2 = __shfl_xor_sync(FULL, m2[s], off);
            int   oi2 = __shfl_xor_sync(FULL, i2[s], off);
            if (om1 > m1[s] || (om1 == m1[s] && oi1 < i1[s])) {
                float tm = m1[s]; int ti = i1[s];
                m1[s] = om1; i1[s] = oi1;
                om1 = tm; oi1 = ti;
            }
            if (om1 > m2[s] || (om1 == m2[s] && oi1 < i2[s])) { m2[s] = om1; i2[s] = oi1; }
            if (om2 > m2[s] || (om2 == m2[s] && oi2 < i2[s])) { m2[s] = om2; i2[s] = oi2; }
        }
    }
    if (q == 0) {
        #pragma unroll
        for (int s = 0; s < 4; s++) {
            int n = n0 + (s >> 1) * 16 + (s & 1) * 8 + r;
            g_cand[0][n] = i1[s];
            g_cand[1][n] = i2[s];
        }
    }
}

// ---------------------------------------------------------------------------
// exact fp32 argmax refinement over tf32 top-2 candidates
// ---------------------------------------------------------------------------
__global__ void refine_kernel(const float* __restrict__ z, float* __restrict__ out) {
    int n = blockIdx.x * 256 + threadIdx.x;
    int b = n >> 12, hw = n & (HW - 1);
    const float* zb = z + (size_t)b * (D * HW) + hw;
    float zr[D];
    #pragma unroll
    for (int c = 0; c < D; c++) zr[c] = zb[(size_t)c * HW];

    float bd = -1e30f; int bi = 0x7fffffff;
    #pragma unroll
    for (int k = 0; k < 2; k++) {
        int e = g_cand[k][n];
        const float4* er = reinterpret_cast<const float4*>(g_embn + (size_t)e * D);
        float d0 = 0.f, d1 = 0.f, d2 = 0.f, d3 = 0.f;
        #pragma unroll
        for (int t = 0; t < D / 4; t++) {
            float4 v = er[t];
            d0 += zr[4 * t + 0] * v.x;
            d1 += zr[4 * t + 1] * v.y;
            d2 += zr[4 * t + 2] * v.z;
            d3 += zr[4 * t + 3] * v.w;
        }
        float dot = (d0 + d1) + (d2 + d3);
        if (dot > bd || (dot == bd && e < bi)) { bd = dot; bi = e; }
    }
    out[NZ + 1 + n] = (float)bi;
    if (n == 0) out[NZ] = 0.0f;
}

// ---------------------------------------------------------------------------
extern "C" void kernel_launch(void* const* d_in, const int* in_sizes, int n_in,
                              void* d_out, int out_size) {
    const float* z   = (const float*)d_in[0];
    const float* emb = (const float*)d_in[1];
    float* out = (float*)d_out;
    (void)in_sizes; (void)n_in; (void)out_size;

    prep_kernel<<<N_E / 4, 128>>>(emb);
    svq_main_kernel<<<CTAS, THREADS>>>(z, out);
    refine_kernel<<<NROWS / 256, 256>>>(z, out);
}

// round 5
// speedup vs baseline: 4.9580x; 1.1747x over previous
#include <cuda_runtime.h>
#include <cuda_bf16.h>
#include <math.h>
#include <stdint.h>

// ============================================================================
// SoftVectorQuantizer via mma.sync fp16 (m16n8k16, fp32 accum), flash-style.
// z[8,64,64,64] f32, embedding[4096,64] f32.
// out = concat(z_q[2097152], entropy(=0), indices[32768] as f32)
//
// fp16 mantissa == tf32 mantissa (10 bits) but full-rate k16 MMA.
// Algebra: unit-norm rows -> logits <= 1 -> fixed shift exp((s-1)/tau);
// final l2norm absorbs softmax denominator. argmax: fp16 top-2 + exact fp32
// refine fused into the kernel tail.
// ============================================================================

#define N_E     4096
#define D       64
#define HW      4096
#define NZ      2097152
#define NROWS   32768
#define CTAS    128          // 256 rows per CTA
#define THREADS 256          // 8 warps x 32 rows
#define NT      64           // embedding tiles of 64
#define CE      20.60992529f // log2(e)/0.07

__device__ float    g_embn[N_E * D];      // normalized embedding (refine)
__device__ uint16_t g_kf[NT * 4096];      // fp16 K B-frags, tile-blocked (8KB/tile)
__device__ uint16_t g_vf[NT * 4096];      // fp16 V B-frags, tile-blocked (8KB/tile)

__device__ __forceinline__ float ex2f(float x) {
    float r; asm("ex2.approx.f32 %0, %1;" : "=f"(r) : "f"(x)); return r;
}
__device__ __forceinline__ uint32_t pack_h2(float lo, float hi) {
    uint32_t r; asm("cvt.rn.f16x2.f32 %0, %1, %2;" : "=r"(r) : "f"(hi), "f"(lo));
    return r;
}
__device__ __forceinline__ uint32_t smem_u32(const void* p) {
    uint32_t a;
    asm("{ .reg .u64 t; cvta.to.shared.u64 t, %1; cvt.u32.u64 %0, t; }"
        : "=r"(a) : "l"(p));
    return a;
}
__device__ __forceinline__ void cpa16(uint32_t dst, const void* src) {
    asm volatile("cp.async.cg.shared.global [%0], [%1], 16;" :: "r"(dst), "l"(src));
}
__device__ __forceinline__ void mma_f16(float c[4], const uint32_t a[4],
                                        uint32_t b0, uint32_t b1) {
    asm volatile(
        "mma.sync.aligned.m16n8k16.row.col.f32.f16.f16.f32 "
        "{%0,%1,%2,%3},{%4,%5,%6,%7},{%8,%9},{%0,%1,%2,%3};"
        : "+f"(c[0]), "+f"(c[1]), "+f"(c[2]), "+f"(c[3])
        : "r"(a[0]), "r"(a[1]), "r"(a[2]), "r"(a[3]), "r"(b0), "r"(b1));
}

// B-frag half-index helpers (within one 64x64 tile, 4096 halves)
// GEMM1 (S = Q . K^T): k-dim = d, n-dim = e
__device__ __forceinline__ int kf_hidx(int e, int d) {
    int u = ((e >> 3) * 4 + (d >> 4)) * 64 +
            ((e & 7) * 4 + ((d & 7) >> 1)) * 2 + ((d >> 3) & 1);
    return u * 2 + (d & 1);
}
// GEMM2 (O += P . V): k-dim = e, n-dim = d
__device__ __forceinline__ int vf_hidx(int e, int d) {
    int u = ((d >> 3) * 4 + (e >> 4)) * 64 +
            ((d & 7) * 4 + ((e & 7) >> 1)) * 2 + ((e >> 3) & 1);
    return u * 2 + (e & 1);
}

// ---------------------------------------------------------------------------
// prep: normalize embedding rows + scatter fp16 B-fragments (once)
// ---------------------------------------------------------------------------
__global__ void prep_kernel(const float* __restrict__ emb) {
    int e = blockIdx.x * 4 + (threadIdx.x >> 5);
    int lane = threadIdx.x & 31;
    float2 v = reinterpret_cast<const float2*>(emb + (size_t)e * D)[lane];
    float s = v.x * v.x + v.y * v.y;
    #pragma unroll
    for (int o = 16; o; o >>= 1) s += __shfl_xor_sync(0xffffffffu, s, o);
    float inv = 1.0f / fmaxf(sqrtf(s), 1e-12f);
    float2 r; r.x = v.x * inv; r.y = v.y * inv;
    reinterpret_cast<float2*>(g_embn + (size_t)e * D)[lane] = r;

    int tile = e >> 6, el = e & 63;
    int d0 = 2 * lane, d1 = 2 * lane + 1;
    __half h0 = __float2half_rn(r.x), h1 = __float2half_rn(r.y);
    uint16_t u0 = *reinterpret_cast<uint16_t*>(&h0);
    uint16_t u1 = *reinterpret_cast<uint16_t*>(&h1);
    g_kf[tile * 4096 + kf_hidx(el, d0)] = u0;
    g_kf[tile * 4096 + kf_hidx(el, d1)] = u1;
    g_vf[tile * 4096 + vf_hidx(el, d0)] = u0;
    g_vf[tile * 4096 + vf_hidx(el, d1)] = u1;
}

// ---------------------------------------------------------------------------
// main fused kernel
// ---------------------------------------------------------------------------
__global__ void __launch_bounds__(THREADS)
svq_main_kernel(const float* __restrict__ z, float* __restrict__ out) {
    __shared__ uint32_t s_kf[2][2048];   // 16 KB
    __shared__ uint32_t s_vf[2][2048];   // 16 KB

    const int tid  = threadIdx.x;
    const int w    = tid >> 5;
    const int lane = tid & 31;
    const int q    = lane & 3;
    const int r    = lane >> 2;
    const unsigned FULL = 0xffffffffu;

    const uint32_t kf_s[2] = {smem_u32(&s_kf[0][0]), smem_u32(&s_kf[1][0])};
    const uint32_t vf_s[2] = {smem_u32(&s_vf[0][0]), smem_u32(&s_vf[1][0])};

    // ---- kick off async copies of tiles 0 and 1 (8KB K + 8KB V each) ----
    #pragma unroll
    for (int tb = 0; tb < 2; tb++) {
        const char* gk = (const char*)g_kf + (size_t)tb * 8192;
        const char* gv = (const char*)g_vf + (size_t)tb * 8192;
        #pragma unroll
        for (int i = 0; i < 2; i++) {
            cpa16(kf_s[tb] + (i * 256 + tid) * 16, gk + (i * 256 + tid) * 16);
            cpa16(vf_s[tb] + (i * 256 + tid) * 16, gv + (i * 256 + tid) * 16);
        }
        asm volatile("cp.async.commit_group;");
    }

    // ---- Q: load 32 rows/warp, l2-normalize, fp16 A-frags (overlaps copies) ----
    const int n0  = blockIdx.x * 256 + w * 32;
    const int bb  = n0 >> 12;
    const int hw0 = n0 & (HW - 1);
    const float* zbase = z + (size_t)bb * D * HW + hw0;

    float zq[2][4][4][2];   // [mi][ks][areg][half]
    float ssq[4] = {0.f, 0.f, 0.f, 0.f};
    #pragma unroll
    for (int mi = 0; mi < 2; mi++)
        #pragma unroll
        for (int ks = 0; ks < 4; ks++)
            #pragma unroll
            for (int a = 0; a < 4; a++) {
                int row = mi * 16 + r + (a & 1) * 8;
                int k   = ks * 16 + 2 * q + ((a & 2) ? 8 : 0);
                float v0 = zbase[(size_t)k * HW + row];
                float v1 = zbase[(size_t)(k + 1) * HW + row];
                zq[mi][ks][a][0] = v0;
                zq[mi][ks][a][1] = v1;
                ssq[mi * 2 + (a & 1)] += v0 * v0 + v1 * v1;
            }
    #pragma unroll
    for (int s = 0; s < 4; s++) {
        ssq[s] += __shfl_xor_sync(FULL, ssq[s], 1);
        ssq[s] += __shfl_xor_sync(FULL, ssq[s], 2);
        ssq[s] = 1.0f / fmaxf(sqrtf(ssq[s]), 1e-12f);
    }
    uint32_t qa[2][4][4];
    #pragma unroll
    for (int mi = 0; mi < 2; mi++)
        #pragma unroll
        for (int ks = 0; ks < 4; ks++)
            #pragma unroll
            for (int a = 0; a < 4; a++) {
                float sc = ssq[mi * 2 + (a & 1)];
                qa[mi][ks][a] = pack_h2(zq[mi][ks][a][0] * sc, zq[mi][ks][a][1] * sc);
            }

    float o[2][8][4];
    #pragma unroll
    for (int mi = 0; mi < 2; mi++)
        #pragma unroll
        for (int di = 0; di < 8; di++)
            #pragma unroll
            for (int c = 0; c < 4; c++) o[mi][di][c] = 0.f;
    float m1[4] = {-1e30f, -1e30f, -1e30f, -1e30f};
    float m2[4] = {-1e30f, -1e30f, -1e30f, -1e30f};
    int   i1[4] = {0, 0, 0, 0}, i2[4] = {0, 0, 0, 0};

    for (int t = 0; t < NT; t++) {
        const int cur = t & 1;
        if (t + 1 < NT) asm volatile("cp.async.wait_group 1;");
        else            asm volatile("cp.async.wait_group 0;");
        __syncthreads();

        const uint32_t* ks_p = s_kf[cur];
        const uint32_t* vs_p = s_vf[cur];

        #pragma unroll
        for (int pi = 0; pi < 4; pi++) {
            // GEMM1: S chunks ni = 2pi, 2pi+1  (16 embeddings)
            float s[2][2][4];
            #pragma unroll
            for (int nih = 0; nih < 2; nih++)
                #pragma unroll
                for (int mi = 0; mi < 2; mi++)
                    #pragma unroll
                    for (int c = 0; c < 4; c++) s[nih][mi][c] = 0.f;
            #pragma unroll
            for (int nih = 0; nih < 2; nih++) {
                const int ni = pi * 2 + nih;
                #pragma unroll
                for (int ks = 0; ks < 4; ks++) {
                    uint2 bk = reinterpret_cast<const uint2*>(ks_p)
                                   [(ni * 4 + ks) * 32 + lane];
                    mma_f16(s[nih][0], qa[0][ks], bk.x, bk.y);
                    mma_f16(s[nih][1], qa[1][ks], bk.x, bk.y);
                }
            }
            // epilogue: top-2 + exp -> fp16 A-frags (layout-aligned, no shuffles)
            uint32_t a[2][4];
            #pragma unroll
            for (int mi = 0; mi < 2; mi++)
                #pragma unroll
                for (int nih = 0; nih < 2; nih++) {
                    float p[4];
                    #pragma unroll
                    for (int c = 0; c < 4; c++) {
                        float sv = s[nih][mi][c];
                        int slot = mi * 2 + (c >> 1);
                        int col  = t * 64 + (pi * 2 + nih) * 8 + 2 * q + (c & 1);
                        if (sv > m2[slot]) {
                            if (sv > m1[slot]) {
                                m2[slot] = m1[slot]; i2[slot] = i1[slot];
                                m1[slot] = sv;       i1[slot] = col;
                            } else { m2[slot] = sv; i2[slot] = col; }
                        }
                        p[c] = ex2f(fmaf(sv, CE, -CE));
                    }
                    a[mi][nih * 2 + 0] = pack_h2(p[0], p[1]);
                    a[mi][nih * 2 + 1] = pack_h2(p[2], p[3]);
                }
            // GEMM2: O += P(k16) * V
            #pragma unroll
            for (int di = 0; di < 8; di++) {
                uint2 bv = reinterpret_cast<const uint2*>(vs_p)
                               [(di * 4 + pi) * 32 + lane];
                mma_f16(o[0][di], a[0], bv.x, bv.y);
                mma_f16(o[1][di], a[1], bv.x, bv.y);
            }
        }
        __syncthreads();

        // issue copy of tile t+2 into the freed buffer
        if (t + 2 < NT) {
            const char* gk = (const char*)g_kf + (size_t)(t + 2) * 8192;
            const char* gv = (const char*)g_vf + (size_t)(t + 2) * 8192;
            #pragma unroll
            for (int i = 0; i < 2; i++) {
                cpa16(kf_s[cur] + (i * 256 + tid) * 16, gk + (i * 256 + tid) * 16);
                cpa16(vf_s[cur] + (i * 256 + tid) * 16, gv + (i * 256 + tid) * 16);
            }
            asm volatile("cp.async.commit_group;");
        }
    }

    // ---- O: per-row l2norm + store ----
    float oss[4] = {0.f, 0.f, 0.f, 0.f};
    #pragma unroll
    for (int mi = 0; mi < 2; mi++)
        #pragma unroll
        for (int di = 0; di < 8; di++) {
            oss[mi * 2 + 0] += o[mi][di][0] * o[mi][di][0] + o[mi][di][1] * o[mi][di][1];
            oss[mi * 2 + 1] += o[mi][di][2] * o[mi][di][2] + o[mi][di][3] * o[mi][di][3];
        }
    #pragma unroll
    for (int s = 0; s < 4; s++) {
        oss[s] += __shfl_xor_sync(FULL, oss[s], 1);
        oss[s] += __shfl_xor_sync(FULL, oss[s], 2);
        oss[s] = 1.0f / fmaxf(sqrtf(oss[s]), 1e-12f);
    }
    float* ob = out + (size_t)bb * D * HW + hw0;
    #pragma unroll
    for (int mi = 0; mi < 2; mi++)
        #pragma unroll
        for (int di = 0; di < 8; di++) {
            int d0 = di * 8 + 2 * q;
            int rl = mi * 16 + r, rh = rl + 8;
            ob[(size_t)d0 * HW + rl]       = o[mi][di][0] * oss[mi * 2];
            ob[(size_t)(d0 + 1) * HW + rl] = o[mi][di][1] * oss[mi * 2];
            ob[(size_t)d0 * HW + rh]       = o[mi][di][2] * oss[mi * 2 + 1];
            ob[(size_t)(d0 + 1) * HW + rh] = o[mi][di][3] * oss[mi * 2 + 1];
        }

    // ---- merge top-2 across the 4 quad lanes of each row ----
    #pragma unroll
    for (int s = 0; s < 4; s++) {
        #pragma unroll
        for (int off = 1; off <= 2; off++) {
            float om1 = __shfl_xor_sync(FULL, m1[s], off);
            int   oi1 = __shfl_xor_sync(FULL, i1[s], off);
            float om2 = __shfl_xor_sync(FULL, m2[s], off);
            int   oi2 = __shfl_xor_sync(FULL, i2[s], off);
            if (om1 > m1[s] || (om1 == m1[s] && oi1 < i1[s])) {
                float tm = m1[s]; int ti = i1[s];
                m1[s] = om1; i1[s] = oi1;
                om1 = tm; oi1 = ti;
            }
            if (om1 > m2[s] || (om1 == m2[s] && oi1 < i2[s])) { m2[s] = om1; i2[s] = oi1; }
            if (om2 > m2[s] || (om2 == m2[s] && oi2 < i2[s])) { m2[s] = om2; i2[s] = oi2; }
        }
    }

    // ---- fused exact-fp32 argmax refine: one lane per row ----
    {
        int sl  = ((lane >> 4) << 1) | ((lane >> 3) & 1);   // slot for row n0+lane
        int src = (lane & 7) * 4;                            // q==0 lane holding it
        int c1, c2;
        #pragma unroll
        for (int s = 0; s < 4; s++) {
            int t1 = __shfl_sync(FULL, i1[s], src);
            int t2 = __shfl_sync(FULL, i2[s], src);
            if (s == sl) { c1 = t1; c2 = t2; }
        }
        const float* zb = zbase + lane;   // row n0 + lane (coalesced per c)
        float zr[D];
        #pragma unroll
        for (int c = 0; c < D; c++) zr[c] = zb[(size_t)c * HW];

        float bd = -1e30f; int bi = 0x7fffffff;
        #pragma unroll
        for (int k = 0; k < 2; k++) {
            int e = (k == 0) ? c1 : c2;
            const float4* er = reinterpret_cast<const float4*>(g_embn + (size_t)e * D);
            float d0 = 0.f, d1 = 0.f, d2 = 0.f, d3 = 0.f;
            #pragma unroll
            for (int tq = 0; tq < D / 4; tq++) {
                float4 v = er[tq];
                d0 += zr[4 * tq + 0] * v.x;
                d1 += zr[4 * tq + 1] * v.y;
                d2 += zr[4 * tq + 2] * v.z;
                d3 += zr[4 * tq + 3] * v.w;
            }
            float dot = (d0 + d1) + (d2 + d3);
            if (dot > bd || (dot == bd && e < bi)) { bd = dot; bi = e; }
        }
        out[NZ + 1 + n0 + lane] = (float)bi;
    }
    if (blockIdx.x == 0 && tid == 0) out[NZ] = 0.0f;
}

// ---------------------------------------------------------------------------
extern "C" void kernel_launch(void* const* d_in, const int* in_sizes, int n_in,
                              void* d_out, int out_size) {
    const float* z   = (const float*)d_in[0];
    const float* emb = (const float*)d_in[1];
    float* out = (float*)d_out;
    (void)in_sizes; (void)n_in; (void)out_size;

    prep_kernel<<<N_E / 4, 128>>>(emb);
    svq_main_kernel<<<CTAS, THREADS>>>(z, out);
}

// round 6
// speedup vs baseline: 7.7919x; 1.5716x over previous
#include <cuda_runtime.h>
#include <cuda_bf16.h>
#include <math.h>
#include <stdint.h>

// ============================================================================
// SoftVectorQuantizer via mma.sync fp16 (m16n8k16, fp32 accum), flash-style.
// z[8,64,64,64] f32, embedding[4096,64] f32.
// out = concat(z_q[2097152], entropy(=0), indices[32768] as f32)
//
// Occupancy-oriented build: 16 rows/warp, 128-thr CTAs, 4 CTAs/SM resident.
// Algebra: unit-norm rows -> logits <= 1 -> fixed shift exp((s-1)/tau);
// final l2norm absorbs softmax denominator. argmax: fp16 top-2 + exact fp32
// refine fused into the kernel tail.
// ============================================================================

#define N_E     4096
#define D       64
#define HW      4096
#define NZ      2097152
#define NROWS   32768
#define CTAS    512          // 64 rows per CTA
#define THREADS 128          // 4 warps x 16 rows
#define NT      64           // embedding tiles of 64
#define CE      20.60992529f // log2(e)/0.07

__device__ float    g_embn[N_E * D];      // normalized embedding (refine)
__device__ uint16_t g_kf[NT * 4096];      // fp16 K B-frags, tile-blocked (8KB/tile)
__device__ uint16_t g_vf[NT * 4096];      // fp16 V B-frags, tile-blocked (8KB/tile)

__device__ __forceinline__ float ex2f(float x) {
    float r; asm("ex2.approx.f32 %0, %1;" : "=f"(r) : "f"(x)); return r;
}
__device__ __forceinline__ uint32_t pack_h2(float lo, float hi) {
    uint32_t r; asm("cvt.rn.f16x2.f32 %0, %1, %2;" : "=r"(r) : "f"(hi), "f"(lo));
    return r;
}
__device__ __forceinline__ uint32_t smem_u32(const void* p) {
    uint32_t a;
    asm("{ .reg .u64 t; cvta.to.shared.u64 t, %1; cvt.u32.u64 %0, t; }"
        : "=r"(a) : "l"(p));
    return a;
}
__device__ __forceinline__ void cpa16(uint32_t dst, const void* src) {
    asm volatile("cp.async.cg.shared.global [%0], [%1], 16;" :: "r"(dst), "l"(src));
}
__device__ __forceinline__ void mma_f16(float c[4], const uint32_t a[4],
                                        uint32_t b0, uint32_t b1) {
    asm volatile(
        "mma.sync.aligned.m16n8k16.row.col.f32.f16.f16.f32 "
        "{%0,%1,%2,%3},{%4,%5,%6,%7},{%8,%9},{%0,%1,%2,%3};"
        : "+f"(c[0]), "+f"(c[1]), "+f"(c[2]), "+f"(c[3])
        : "r"(a[0]), "r"(a[1]), "r"(a[2]), "r"(a[3]), "r"(b0), "r"(b1));
}

// B-frag half-index helpers (within one 64x64 tile, 4096 halves)
// GEMM1 (S = Q . K^T): k-dim = d, n-dim = e
__device__ __forceinline__ int kf_hidx(int e, int d) {
    int u = ((e >> 3) * 4 + (d >> 4)) * 64 +
            ((e & 7) * 4 + ((d & 7) >> 1)) * 2 + ((d >> 3) & 1);
    return u * 2 + (d & 1);
}
// GEMM2 (O += P . V): k-dim = e, n-dim = d
__device__ __forceinline__ int vf_hidx(int e, int d) {
    int u = ((d >> 3) * 4 + (e >> 4)) * 64 +
            ((d & 7) * 4 + ((e & 7) >> 1)) * 2 + ((e >> 3) & 1);
    return u * 2 + (e & 1);
}

// ---------------------------------------------------------------------------
// prep: normalize embedding rows + scatter fp16 B-fragments (once)
// ---------------------------------------------------------------------------
__global__ void prep_kernel(const float* __restrict__ emb) {
    int e = blockIdx.x * 4 + (threadIdx.x >> 5);
    int lane = threadIdx.x & 31;
    float2 v = reinterpret_cast<const float2*>(emb + (size_t)e * D)[lane];
    float s = v.x * v.x + v.y * v.y;
    #pragma unroll
    for (int o = 16; o; o >>= 1) s += __shfl_xor_sync(0xffffffffu, s, o);
    float inv = 1.0f / fmaxf(sqrtf(s), 1e-12f);
    float2 r; r.x = v.x * inv; r.y = v.y * inv;
    reinterpret_cast<float2*>(g_embn + (size_t)e * D)[lane] = r;

    int tile = e >> 6, el = e & 63;
    int d0 = 2 * lane, d1 = 2 * lane + 1;
    __half h0 = __float2half_rn(r.x), h1 = __float2half_rn(r.y);
    uint16_t u0 = *reinterpret_cast<uint16_t*>(&h0);
    uint16_t u1 = *reinterpret_cast<uint16_t*>(&h1);
    g_kf[tile * 4096 + kf_hidx(el, d0)] = u0;
    g_kf[tile * 4096 + kf_hidx(el, d1)] = u1;
    g_vf[tile * 4096 + vf_hidx(el, d0)] = u0;
    g_vf[tile * 4096 + vf_hidx(el, d1)] = u1;
}

// ---------------------------------------------------------------------------
// main fused kernel
// ---------------------------------------------------------------------------
__global__ void __launch_bounds__(THREADS, 4)
svq_main_kernel(const float* __restrict__ z, float* __restrict__ out) {
    __shared__ uint32_t s_kf[2][2048];   // 16 KB
    __shared__ uint32_t s_vf[2][2048];   // 16 KB
    __shared__ int      s_cand[64][2];   // argmax candidates

    const int tid  = threadIdx.x;
    const int w    = tid >> 5;
    const int lane = tid & 31;
    const int q    = lane & 3;
    const int r    = lane >> 2;
    const unsigned FULL = 0xffffffffu;

    const uint32_t kf_s[2] = {smem_u32(&s_kf[0][0]), smem_u32(&s_kf[1][0])};
    const uint32_t vf_s[2] = {smem_u32(&s_vf[0][0]), smem_u32(&s_vf[1][0])};

    // ---- kick off async copies of tiles 0 and 1 (8KB K + 8KB V each) ----
    #pragma unroll
    for (int tb = 0; tb < 2; tb++) {
        const char* gk = (const char*)g_kf + (size_t)tb * 8192;
        const char* gv = (const char*)g_vf + (size_t)tb * 8192;
        #pragma unroll
        for (int i = 0; i < 4; i++) {
            cpa16(kf_s[tb] + (i * 128 + tid) * 16, gk + (i * 128 + tid) * 16);
            cpa16(vf_s[tb] + (i * 128 + tid) * 16, gv + (i * 128 + tid) * 16);
        }
        asm volatile("cp.async.commit_group;");
    }

    // ---- Q: 16 rows/warp, l2-normalize, fp16 A-frags (overlaps copies) ----
    const int n0  = blockIdx.x * 64;          // first row of this CTA
    const int bb  = n0 >> 12;
    const int hw0 = n0 & (HW - 1);
    const float* zbase = z + (size_t)bb * D * HW + hw0;
    const int wrow = w * 16;                  // warp's first row (CTA-local)

    uint32_t qa[4][4];
    {
        float zq[4][4][2];
        float ssq[2] = {0.f, 0.f};
        #pragma unroll
        for (int ks = 0; ks < 4; ks++)
            #pragma unroll
            for (int a = 0; a < 4; a++) {
                int row = wrow + r + (a & 1) * 8;
                int k   = ks * 16 + 2 * q + ((a & 2) ? 8 : 0);
                float v0 = zbase[(size_t)k * HW + row];
                float v1 = zbase[(size_t)(k + 1) * HW + row];
                zq[ks][a][0] = v0;
                zq[ks][a][1] = v1;
                ssq[a & 1] += v0 * v0 + v1 * v1;
            }
        #pragma unroll
        for (int s = 0; s < 2; s++) {
            ssq[s] += __shfl_xor_sync(FULL, ssq[s], 1);
            ssq[s] += __shfl_xor_sync(FULL, ssq[s], 2);
            ssq[s] = 1.0f / fmaxf(sqrtf(ssq[s]), 1e-12f);
        }
        #pragma unroll
        for (int ks = 0; ks < 4; ks++)
            #pragma unroll
            for (int a = 0; a < 4; a++) {
                float sc = ssq[a & 1];
                qa[ks][a] = pack_h2(zq[ks][a][0] * sc, zq[ks][a][1] * sc);
            }
    }

    float o[8][4];
    #pragma unroll
    for (int di = 0; di < 8; di++)
        #pragma unroll
        for (int c = 0; c < 4; c++) o[di][c] = 0.f;
    float m1[2] = {-1e30f, -1e30f}, m2[2] = {-1e30f, -1e30f};
    int   i1[2] = {0, 0}, i2[2] = {0, 0};

    for (int t = 0; t < NT; t++) {
        const int cur = t & 1;
        if (t + 1 < NT) asm volatile("cp.async.wait_group 1;");
        else            asm volatile("cp.async.wait_group 0;");
        __syncthreads();

        const uint32_t* ks_p = s_kf[cur];
        const uint32_t* vs_p = s_vf[cur];

        #pragma unroll
        for (int pi = 0; pi < 4; pi++) {
            // GEMM1: two n8 chunks (16 embeddings)
            float s[2][4];
            #pragma unroll
            for (int nih = 0; nih < 2; nih++)
                #pragma unroll
                for (int c = 0; c < 4; c++) s[nih][c] = 0.f;
            #pragma unroll
            for (int nih = 0; nih < 2; nih++) {
                const int ni = pi * 2 + nih;
                #pragma unroll
                for (int ks = 0; ks < 4; ks++) {
                    uint2 bk = reinterpret_cast<const uint2*>(ks_p)
                                   [(ni * 4 + ks) * 32 + lane];
                    mma_f16(s[nih], qa[ks], bk.x, bk.y);
                }
            }
            // exp + pack FIRST (feeds GEMM2 asap) ...
            uint32_t a[4];
            #pragma unroll
            for (int nih = 0; nih < 2; nih++) {
                float p0 = ex2f(fmaf(s[nih][0], CE, -CE));
                float p1 = ex2f(fmaf(s[nih][1], CE, -CE));
                float p2 = ex2f(fmaf(s[nih][2], CE, -CE));
                float p3 = ex2f(fmaf(s[nih][3], CE, -CE));
                a[nih * 2 + 0] = pack_h2(p0, p1);
                a[nih * 2 + 1] = pack_h2(p2, p3);
            }
            // GEMM2: O += P(k16) * V
            #pragma unroll
            for (int di = 0; di < 8; di++) {
                uint2 bv = reinterpret_cast<const uint2*>(vs_p)
                               [(di * 4 + pi) * 32 + lane];
                mma_f16(o[di], a, bv.x, bv.y);
            }
            // ... top-2 tracking AFTER (doesn't gate the MMAs)
            #pragma unroll
            for (int nih = 0; nih < 2; nih++)
                #pragma unroll
                for (int c = 0; c < 4; c++) {
                    float sv = s[nih][c];
                    int slot = c >> 1;
                    if (sv > m2[slot]) {
                        int col = t * 64 + (pi * 2 + nih) * 8 + 2 * q + (c & 1);
                        if (sv > m1[slot]) {
                            m2[slot] = m1[slot]; i2[slot] = i1[slot];
                            m1[slot] = sv;       i1[slot] = col;
                        } else { m2[slot] = sv; i2[slot] = col; }
                    }
                }
        }
        __syncthreads();

        // issue copy of tile t+2 into the freed buffer
        if (t + 2 < NT) {
            const char* gk = (const char*)g_kf + (size_t)(t + 2) * 8192;
            const char* gv = (const char*)g_vf + (size_t)(t + 2) * 8192;
            #pragma unroll
            for (int i = 0; i < 4; i++) {
                cpa16(kf_s[cur] + (i * 128 + tid) * 16, gk + (i * 128 + tid) * 16);
                cpa16(vf_s[cur] + (i * 128 + tid) * 16, gv + (i * 128 + tid) * 16);
            }
            asm volatile("cp.async.commit_group;");
        }
    }

    // ---- O: per-row l2norm + store ----
    {
        float oss[2] = {0.f, 0.f};
        #pragma unroll
        for (int di = 0; di < 8; di++) {
            oss[0] += o[di][0] * o[di][0] + o[di][1] * o[di][1];
            oss[1] += o[di][2] * o[di][2] + o[di][3] * o[di][3];
        }
        #pragma unroll
        for (int s = 0; s < 2; s++) {
            oss[s] += __shfl_xor_sync(FULL, oss[s], 1);
            oss[s] += __shfl_xor_sync(FULL, oss[s], 2);
            oss[s] = 1.0f / fmaxf(sqrtf(oss[s]), 1e-12f);
        }
        float* ob = out + (size_t)bb * D * HW + hw0;
        #pragma unroll
        for (int di = 0; di < 8; di++) {
            int d0 = di * 8 + 2 * q;
            int rl = wrow + r, rh = rl + 8;
            ob[(size_t)d0 * HW + rl]       = o[di][0] * oss[0];
            ob[(size_t)(d0 + 1) * HW + rl] = o[di][1] * oss[0];
            ob[(size_t)d0 * HW + rh]       = o[di][2] * oss[1];
            ob[(size_t)(d0 + 1) * HW + rh] = o[di][3] * oss[1];
        }
    }

    // ---- merge top-2 across the 4 quad lanes of each row ----
    #pragma unroll
    for (int s = 0; s < 2; s++) {
        #pragma unroll
        for (int off = 1; off <= 2; off++) {
            float om1 = __shfl_xor_sync(FULL, m1[s], off);
            int   oi1 = __shfl_xor_sync(FULL, i1[s], off);
            float om2 = __shfl_xor_sync(FULL, m2[s], off);
            int   oi2 = __shfl_xor_sync(FULL, i2[s], off);
            if (om1 > m1[s] || (om1 == m1[s] && oi1 < i1[s])) {
                float tm = m1[s]; int ti = i1[s];
                m1[s] = om1; i1[s] = oi1;
                om1 = tm; oi1 = ti;
            }
            if (om1 > m2[s] || (om1 == m2[s] && oi1 < i2[s])) { m2[s] = om1; i2[s] = oi1; }
            if (om2 > m2[s] || (om2 == m2[s] && oi2 < i2[s])) { m2[s] = om2; i2[s] = oi2; }
        }
    }
    if (q == 0) {
        s_cand[wrow + r][0]     = i1[0];
        s_cand[wrow + r][1]     = i2[0];
        s_cand[wrow + r + 8][0] = i1[1];
        s_cand[wrow + r + 8][1] = i2[1];
    }
    __syncthreads();

    // ---- fused exact-fp32 argmax refine: 2 threads per row ----
    {
        const int row  = tid >> 1;       // CTA-local row 0..63
        const int half = tid & 1;        // channel half
        const int c1 = s_cand[row][0], c2 = s_cand[row][1];
        const float* zb = zbase + row + (size_t)(half * 32) * HW;
        float zr[32];
        #pragma unroll
        for (int c = 0; c < 32; c++) zr[c] = zb[(size_t)c * HW];

        float bd = -1e30f; int bi = 0x7fffffff;
        #pragma unroll
        for (int k = 0; k < 2; k++) {
            int e = (k == 0) ? c1 : c2;
            const float4* er = reinterpret_cast<const float4*>(
                g_embn + (size_t)e * D + half * 32);
            float d0 = 0.f, d1 = 0.f, d2 = 0.f, d3 = 0.f;
            #pragma unroll
            for (int tq = 0; tq < 8; tq++) {
                float4 v = er[tq];
                d0 += zr[4 * tq + 0] * v.x;
                d1 += zr[4 * tq + 1] * v.y;
                d2 += zr[4 * tq + 2] * v.z;
                d3 += zr[4 * tq + 3] * v.w;
            }
            float part = (d0 + d1) + (d2 + d3);
            float dot = part + __shfl_xor_sync(FULL, part, 1);
            if (dot > bd || (dot == bd && e < bi)) { bd = dot; bi = e; }
        }
        if (half == 0) out[NZ + 1 + n0 + row] = (float)bi;
    }
    if (blockIdx.x == 0 && tid == 0) out[NZ] = 0.0f;
}

// ---------------------------------------------------------------------------
extern "C" void kernel_launch(void* const* d_in, const int* in_sizes, int n_in,
                              void* d_out, int out_size) {
    const float* z   = (const float*)d_in[0];
    const float* emb = (const float*)d_in[1];
    float* out = (float*)d_out;
    (void)in_sizes; (void)n_in; (void)out_size;

    prep_kernel<<<N_E / 4, 128>>>(emb);
    svq_main_kernel<<<CTAS, THREADS>>>(z, out);
}

// round 7
// speedup vs baseline: 7.8694x; 1.0099x over previous
#include <cuda_runtime.h>
#include <cuda_bf16.h>
#include <math.h>
#include <stdint.h>

// ============================================================================
// SoftVectorQuantizer via mma.sync fp16 (m16n8k16, fp32 accum), flash-style.
// z[8,64,64,64] f32, embedding[4096,64] f32.
// out = concat(z_q[2097152], entropy(=0), indices[32768] as f32)
//
// Issue-slot diet build: f16x2 ex2 (half MUFU + half CVT), uint4 B-frag loads
// (half LDS), gated top-2 (half compare cost). 4 CTAs/SM resident.
// Algebra: unit-norm rows -> logits <= 1 -> fixed shift exp((s-1)/tau);
// final l2norm absorbs softmax denominator. argmax: fp16 top-2 + exact fp32
// refine fused into the kernel tail.
// ============================================================================

#define N_E     4096
#define D       64
#define HW      4096
#define NZ      2097152
#define NROWS   32768
#define CTAS    512          // 64 rows per CTA
#define THREADS 128          // 4 warps x 16 rows
#define NT      64           // embedding tiles of 64
#define CE      20.60992529f // log2(e)/0.07

__device__ float    g_embn[N_E * D];      // normalized embedding (refine)
__device__ uint32_t g_kf[NT * 2048];      // fp16 K B-frags (uint4-grouped), 8KB/tile
__device__ uint16_t g_vf[NT * 4096];      // fp16 V B-frags (uint4-grouped), 8KB/tile

__device__ __forceinline__ uint32_t ex2_h2(uint32_t h) {
    uint32_t r; asm("ex2.approx.f16x2 %0, %1;" : "=r"(r) : "r"(h)); return r;
}
__device__ __forceinline__ uint32_t pack_h2(float lo, float hi) {
    uint32_t r; asm("cvt.rn.f16x2.f32 %0, %1, %2;" : "=r"(r) : "f"(hi), "f"(lo));
    return r;
}
__device__ __forceinline__ uint32_t smem_u32(const void* p) {
    uint32_t a;
    asm("{ .reg .u64 t; cvta.to.shared.u64 t, %1; cvt.u32.u64 %0, t; }"
        : "=r"(a) : "l"(p));
    return a;
}
__device__ __forceinline__ void cpa16(uint32_t dst, const void* src) {
    asm volatile("cp.async.cg.shared.global [%0], [%1], 16;" :: "r"(dst), "l"(src));
}
__device__ __forceinline__ void mma_f16(float c[4], const uint32_t a[4],
                                        uint32_t b0, uint32_t b1) {
    asm volatile(
        "mma.sync.aligned.m16n8k16.row.col.f32.f16.f16.f32 "
        "{%0,%1,%2,%3},{%4,%5,%6,%7},{%8,%9},{%0,%1,%2,%3};"
        : "+f"(c[0]), "+f"(c[1]), "+f"(c[2]), "+f"(c[3])
        : "r"(a[0]), "r"(a[1]), "r"(a[2]), "r"(a[3]), "r"(b0), "r"(b1));
}

// Fragment half-index helpers (uint4-grouped layouts, 4096 halves per tile).
// GEMM1 (S = Q.K^T): n-dim = e, k-dim = d.
// Load: uint4 at [(ni*2+kp)*32 + lane], lane=(e&7)*4+((d>>1)&3);
//   .x/.y = b0/b1 of k-step 2kp, .z/.w = b0/b1 of k-step 2kp+1.
__device__ __forceinline__ int kf_hidx(int e, int d) {
    return ((((e >> 3) * 2 + (d >> 5)) * 32 + (e & 7) * 4 + ((d >> 1) & 3)) * 8)
           + ((d >> 4) & 1) * 4 + ((d >> 3) & 1) * 2 + (d & 1);
}
// GEMM2 (O += P.V): n-dim = d, k-dim = e.
// Load: uint4 at [(dp*4+pi)*32 + lane], lane=(d&7)*4+((e>>1)&3);
//   .x/.y = b0/b1 of n-chunk 2dp, .z/.w = b0/b1 of n-chunk 2dp+1.
__device__ __forceinline__ int vf_hidx(int e, int d) {
    return ((((d >> 4) * 4 + (e >> 4)) * 32 + (d & 7) * 4 + ((e >> 1) & 3)) * 8)
           + ((d >> 3) & 1) * 4 + ((e >> 3) & 1) * 2 + (e & 1);
}

// ---------------------------------------------------------------------------
// prep: normalize embedding rows + scatter fp16 B-fragments (once)
// ---------------------------------------------------------------------------
__global__ void prep_kernel(const float* __restrict__ emb) {
    int e = blockIdx.x * 4 + (threadIdx.x >> 5);
    int lane = threadIdx.x & 31;
    float2 v = reinterpret_cast<const float2*>(emb + (size_t)e * D)[lane];
    float s = v.x * v.x + v.y * v.y;
    #pragma unroll
    for (int o = 16; o; o >>= 1) s += __shfl_xor_sync(0xffffffffu, s, o);
    float inv = 1.0f / fmaxf(sqrtf(s), 1e-12f);
    float2 r; r.x = v.x * inv; r.y = v.y * inv;
    reinterpret_cast<float2*>(g_embn + (size_t)e * D)[lane] = r;

    int tile = e >> 6, el = e & 63;
    int d0 = 2 * lane, d1 = 2 * lane + 1;
    __half h0 = __float2half_rn(r.x), h1 = __float2half_rn(r.y);
    uint16_t u0 = *reinterpret_cast<uint16_t*>(&h0);
    uint16_t u1 = *reinterpret_cast<uint16_t*>(&h1);
    // kf: d0 even, d1 = d0+1 -> adjacent halves of one uint32
    g_kf[tile * 2048 + (kf_hidx(el, d0) >> 1)] = (uint32_t)u0 | ((uint32_t)u1 << 16);
    g_vf[tile * 4096 + vf_hidx(el, d0)] = u0;
    g_vf[tile * 4096 + vf_hidx(el, d1)] = u1;
}

// ---------------------------------------------------------------------------
// main fused kernel
// ---------------------------------------------------------------------------
__global__ void __launch_bounds__(THREADS, 4)
svq_main_kernel(const float* __restrict__ z, float* __restrict__ out) {
    __shared__ uint4 s_kf[2][512];   // 16 KB
    __shared__ uint4 s_vf[2][512];   // 16 KB
    __shared__ int   s_cand[64][2];  // argmax candidates

    const int tid  = threadIdx.x;
    const int w    = tid >> 5;
    const int lane = tid & 31;
    const int q    = lane & 3;
    const int r    = lane >> 2;
    const unsigned FULL = 0xffffffffu;

    const uint32_t kf_s[2] = {smem_u32(&s_kf[0][0]), smem_u32(&s_kf[1][0])};
    const uint32_t vf_s[2] = {smem_u32(&s_vf[0][0]), smem_u32(&s_vf[1][0])};

    // ---- kick off async copies of tiles 0 and 1 (8KB K + 8KB V each) ----
    #pragma unroll
    for (int tb = 0; tb < 2; tb++) {
        const char* gk = (const char*)g_kf + (size_t)tb * 8192;
        const char* gv = (const char*)g_vf + (size_t)tb * 8192;
        #pragma unroll
        for (int i = 0; i < 4; i++) {
            cpa16(kf_s[tb] + (i * 128 + tid) * 16, gk + (i * 128 + tid) * 16);
            cpa16(vf_s[tb] + (i * 128 + tid) * 16, gv + (i * 128 + tid) * 16);
        }
        asm volatile("cp.async.commit_group;");
    }

    // ---- Q: 16 rows/warp, l2-normalize, fp16 A-frags (overlaps copies) ----
    const int n0  = blockIdx.x * 64;          // first row of this CTA
    const int bb  = n0 >> 12;
    const int hw0 = n0 & (HW - 1);
    const float* zbase = z + (size_t)bb * D * HW + hw0;
    const int wrow = w * 16;                  // warp's first row (CTA-local)

    uint32_t qa[4][4];
    {
        float zq[4][4][2];
        float ssq[2] = {0.f, 0.f};
        #pragma unroll
        for (int ks = 0; ks < 4; ks++)
            #pragma unroll
            for (int a = 0; a < 4; a++) {
                int row = wrow + r + (a & 1) * 8;
                int k   = ks * 16 + 2 * q + ((a & 2) ? 8 : 0);
                float v0 = zbase[(size_t)k * HW + row];
                float v1 = zbase[(size_t)(k + 1) * HW + row];
                zq[ks][a][0] = v0;
                zq[ks][a][1] = v1;
                ssq[a & 1] += v0 * v0 + v1 * v1;
            }
        #pragma unroll
        for (int s = 0; s < 2; s++) {
            ssq[s] += __shfl_xor_sync(FULL, ssq[s], 1);
            ssq[s] += __shfl_xor_sync(FULL, ssq[s], 2);
            ssq[s] = 1.0f / fmaxf(sqrtf(ssq[s]), 1e-12f);
        }
        #pragma unroll
        for (int ks = 0; ks < 4; ks++)
            #pragma unroll
            for (int a = 0; a < 4; a++) {
                float sc = ssq[a & 1];
                qa[ks][a] = pack_h2(zq[ks][a][0] * sc, zq[ks][a][1] * sc);
            }
    }

    float o[8][4];
    #pragma unroll
    for (int di = 0; di < 8; di++)
        #pragma unroll
        for (int c = 0; c < 4; c++) o[di][c] = 0.f;
    float m1[2] = {-1e30f, -1e30f}, m2[2] = {-1e30f, -1e30f};
    int   i1[2] = {0, 0}, i2[2] = {0, 0};

    for (int t = 0; t < NT; t++) {
        const int cur = t & 1;
        if (t + 1 < NT) asm volatile("cp.async.wait_group 1;");
        else            asm volatile("cp.async.wait_group 0;");
        __syncthreads();

        const uint4* ks4 = s_kf[cur];
        const uint4* vs4 = s_vf[cur];

        #pragma unroll
        for (int pi = 0; pi < 4; pi++) {
            // GEMM1: two n8 chunks (16 embeddings), uint4 loads (2 k-steps each)
            float s[2][4];
            #pragma unroll
            for (int nih = 0; nih < 2; nih++)
                #pragma unroll
                for (int c = 0; c < 4; c++) s[nih][c] = 0.f;
            #pragma unroll
            for (int nih = 0; nih < 2; nih++) {
                const int ni = pi * 2 + nih;
                #pragma unroll
                for (int kp = 0; kp < 2; kp++) {
                    uint4 bk = ks4[(ni * 2 + kp) * 32 + lane];
                    mma_f16(s[nih], qa[2 * kp],     bk.x, bk.y);
                    mma_f16(s[nih], qa[2 * kp + 1], bk.z, bk.w);
                }
            }
            // exp: fp32 fma -> f16x2 pack -> one MUFU per pair; output IS the A-frag
            uint32_t a[4];
            #pragma unroll
            for (int nih = 0; nih < 2; nih++) {
                float t0 = fmaf(s[nih][0], CE, -CE);
                float t1 = fmaf(s[nih][1], CE, -CE);
                float t2 = fmaf(s[nih][2], CE, -CE);
                float t3 = fmaf(s[nih][3], CE, -CE);
                a[nih * 2 + 0] = ex2_h2(pack_h2(t0, t1));
                a[nih * 2 + 1] = ex2_h2(pack_h2(t2, t3));
            }
            // GEMM2: O += P(k16) * V, uint4 loads (2 n-chunks each)
            #pragma unroll
            for (int dp = 0; dp < 4; dp++) {
                uint4 bv = vs4[(dp * 4 + pi) * 32 + lane];
                mma_f16(o[2 * dp],     a, bv.x, bv.y);
                mma_f16(o[2 * dp + 1], a, bv.z, bv.w);
            }
            // top-2 tracking, gated by pair-max (common path = 2 ops / 2 values)
            #pragma unroll
            for (int nih = 0; nih < 2; nih++)
                #pragma unroll
                for (int slot = 0; slot < 2; slot++) {
                    float s0 = s[nih][slot * 2], s1 = s[nih][slot * 2 + 1];
                    if (fmaxf(s0, s1) > m2[slot]) {
                        int col0 = t * 64 + (pi * 2 + nih) * 8 + 2 * q;
                        if (s0 > m2[slot]) {
                            if (s0 > m1[slot]) {
                                m2[slot] = m1[slot]; i2[slot] = i1[slot];
                                m1[slot] = s0;       i1[slot] = col0;
                            } else { m2[slot] = s0; i2[slot] = col0; }
                        }
                        if (s1 > m2[slot]) {
                            if (s1 > m1[slot]) {
                                m2[slot] = m1[slot]; i2[slot] = i1[slot];
                                m1[slot] = s1;       i1[slot] = col0 + 1;
                            } else { m2[slot] = s1; i2[slot] = col0 + 1; }
                        }
                    }
                }
        }
        __syncthreads();

        // issue copy of tile t+2 into the freed buffer
        if (t + 2 < NT) {
            const char* gk = (const char*)g_kf + (size_t)(t + 2) * 8192;
            const char* gv = (const char*)g_vf + (size_t)(t + 2) * 8192;
            #pragma unroll
            for (int i = 0; i < 4; i++) {
                cpa16(kf_s[cur] + (i * 128 + tid) * 16, gk + (i * 128 + tid) * 16);
                cpa16(vf_s[cur] + (i * 128 + tid) * 16, gv + (i * 128 + tid) * 16);
            }
            asm volatile("cp.async.commit_group;");
        }
    }

    // ---- O: per-row l2norm + store ----
    {
        float oss[2] = {0.f, 0.f};
        #pragma unroll
        for (int di = 0; di < 8; di++) {
            oss[0] += o[di][0] * o[di][0] + o[di][1] * o[di][1];
            oss[1] += o[di][2] * o[di][2] + o[di][3] * o[di][3];
        }
        #pragma unroll
        for (int s = 0; s < 2; s++) {
            oss[s] += __shfl_xor_sync(FULL, oss[s], 1);
            oss[s] += __shfl_xor_sync(FULL, oss[s], 2);
            oss[s] = 1.0f / fmaxf(sqrtf(oss[s]), 1e-12f);
        }
        float* ob = out + (size_t)bb * D * HW + hw0;
        #pragma unroll
        for (int di = 0; di < 8; di++) {
            int d0 = di * 8 + 2 * q;
            int rl = wrow + r, rh = rl + 8;
            ob[(size_t)d0 * HW + rl]       = o[di][0] * oss[0];
            ob[(size_t)(d0 + 1) * HW + rl] = o[di][1] * oss[0];
            ob[(size_t)d0 * HW + rh]       = o[di][2] * oss[1];
            ob[(size_t)(d0 + 1) * HW + rh] = o[di][3] * oss[1];
        }
    }

    // ---- merge top-2 across the 4 quad lanes of each row ----
    #pragma unroll
    for (int s = 0; s < 2; s++) {
        #pragma unroll
        for (int off = 1; off <= 2; off++) {
            float om1 = __shfl_xor_sync(FULL, m1[s], off);
            int   oi1 = __shfl_xor_sync(FULL, i1[s], off);
            float om2 = __shfl_xor_sync(FULL, m2[s], off);
            int   oi2 = __shfl_xor_sync(FULL, i2[s], off);
            if (om1 > m1[s] || (om1 == m1[s] && oi1 < i1[s])) {
                float tm = m1[s]; int ti = i1[s];
                m1[s] = om1; i1[s] = oi1;
                om1 = tm; oi1 = ti;
            }
            if (om1 > m2[s] || (om1 == m2[s] && oi1 < i2[s])) { m2[s] = om1; i2[s] = oi1; }
            if (om2 > m2[s] || (om2 == m2[s] && oi2 < i2[s])) { m2[s] = om2; i2[s] = oi2; }
        }
    }
    if (q == 0) {
        s_cand[wrow + r][0]     = i1[0];
        s_cand[wrow + r][1]     = i2[0];
        s_cand[wrow + r + 8][0] = i1[1];
        s_cand[wrow + r + 8][1] = i2[1];
    }
    __syncthreads();

    // ---- fused exact-fp32 argmax refine: 2 threads per row ----
    {
        const int row  = tid >> 1;       // CTA-local row 0..63
        const int half = tid & 1;        // channel half
        const int c1 = s_cand[row][0], c2 = s_cand[row][1];
        const float* zb = zbase + row + (size_t)(half * 32) * HW;
        float zr[32];
        #pragma unroll
        for (int c = 0; c < 32; c++) zr[c] = zb[(size_t)c * HW];

        float bd = -1e30f; int bi = 0x7fffffff;
        #pragma unroll
        for (int k = 0; k < 2; k++) {
            int e = (k == 0) ? c1 : c2;
            const float4* er = reinterpret_cast<const float4*>(
                g_embn + (size_t)e * D + half * 32);
            float d0 = 0.f, d1 = 0.f, d2 = 0.f, d3 = 0.f;
            #pragma unroll
            for (int tq = 0; tq < 8; tq++) {
                float4 v = er[tq];
                d0 += zr[4 * tq + 0] * v.x;
                d1 += zr[4 * tq + 1] * v.y;
                d2 += zr[4 * tq + 2] * v.z;
                d3 += zr[4 * tq + 3] * v.w;
            }
            float part = (d0 + d1) + (d2 + d3);
            float dot = part + __shfl_xor_sync(FULL, part, 1);
            if (dot > bd || (dot == bd && e < bi)) { bd = dot; bi = e; }
        }
        if (half == 0) out[NZ + 1 + n0 + row] = (float)bi;
    }
    if (blockIdx.x == 0 && tid == 0) out[NZ] = 0.0f;
}

// ---------------------------------------------------------------------------
extern "C" void kernel_launch(void* const* d_in, const int* in_sizes, int n_in,
                              void* d_out, int out_size) {
    const float* z   = (const float*)d_in[0];
    const float* emb = (const float*)d_in[1];
    float* out = (float*)d_out;
    (void)in_sizes; (void)n_in; (void)out_size;

    prep_kernel<<<N_E / 4, 128>>>(emb);
    svq_main_kernel<<<CTAS, THREADS>>>(z, out);
}